// round 9
// baseline (speedup 1.0000x reference)
#include <cuda_runtime.h>
#include <cuda_fp16.h>

// ---------------------------------------------------------------------------
// SSIM 3D, 11-tap separable Gaussian, VALID. Round 9:
// R7 numerics (fp32 accumulation, fp16 storage) +
//   pass1: 16-row tiles / 256 thr (MLP 6)
//   pass3: strip 7 (35 accums -> ~64 regs -> 4 blocks/SM, 4x loads in flight)
// ---------------------------------------------------------------------------

__device__ constexpr float CG[11] = {
    0.0010283817f, 0.0075987700f, 0.0360007700f, 0.1093607000f,
    0.2130055500f, 0.2660117200f,
    0.2130055500f, 0.1093607000f, 0.0360007700f, 0.0075987700f,
    0.0010283817f
};

// s1: [f][n][d][h(192)][w(184 pad, 182 valid)]   half
// s2: [f][n][d][oh(182)][w(184 pad, 182 valid)]  half
static const size_t FS1 = (size_t)2 * 192 * 192 * 184;   // 13,565,952 halves
static const size_t FS2 = (size_t)2 * 192 * 182 * 184;   // 12,859,392 halves
__device__ __half d_s1[5 * FS1];
__device__ __half d_s2[5 * FS2];

__device__ unsigned d_minbits;
__device__ unsigned d_maxbits;
__device__ float    d_c1c2[2];
__device__ float    d_bsum[6729];

// ---------------------------------------------------------------------------

__global__ void init_kernel() {
    d_minbits = 0xFFFFFFFFu;
    d_maxbits = 0u;
}

__device__ __forceinline__ float mono2f(unsigned u) {
    return (u & 0x80000000u) ? __uint_as_float(u ^ 0x80000000u)
                             : __uint_as_float(~u);
}
__device__ __forceinline__ void mono_acc(float f, unsigned& mn, unsigned& mx) {
    unsigned u = __float_as_uint(f);
    u = (u & 0x80000000u) ? ~u : (u | 0x80000000u);
    mn = min(mn, u);
    mx = max(mx, u);
}

__global__ void const_kernel() {
    float mx = mono2f(d_maxbits);
    float mn = mono2f(d_minbits);
    float max_val = (mx > 128.0f) ? 255.0f : 1.0f;
    float min_val = (mn < -0.5f) ? -1.0f : 0.0f;
    float L = max_val - min_val;
    float c1 = 0.01f * L, c2 = 0.03f * L;
    d_c1c2[0] = c1 * c1;
    d_c1c2[1] = c2 * c2;
}

// ---------------------------------------------------------------------------
// Pass 1: W conv + 5 products + img1 min/max. Block = (n,d, 16 h-rows).
// 256 threads; 6 independent float4 loads per thread; half2 stores.
// ---------------------------------------------------------------------------
__global__ void __launch_bounds__(256) pass1_kernel(
    const float* __restrict__ img1, const float* __restrict__ img2) {
    __shared__ float sx[16 * 192];
    __shared__ float sy[16 * 192];

    int hg = blockIdx.x % 12;
    int nd = blockIdx.x / 12;          // n*192 + d
    int h0 = hg * 16;
    size_t base = ((size_t)nd * 192 + h0) * 192;
    int tid = threadIdx.x;

    unsigned lmin = 0xFFFFFFFFu, lmax = 0u;
    const float4* p1 = (const float4*)(img1 + base);
    const float4* p2 = (const float4*)(img2 + base);
    #pragma unroll
    for (int j = 0; j < 3; j++) {
        int idx = tid + j * 256;       // 0..767 float4
        float4 a = __ldg(&p1[idx]);
        float4 b = __ldg(&p2[idx]);
        ((float4*)sx)[idx] = a;
        ((float4*)sy)[idx] = b;
        mono_acc(a.x, lmin, lmax); mono_acc(a.y, lmin, lmax);
        mono_acc(a.z, lmin, lmax); mono_acc(a.w, lmin, lmax);
    }
    __syncthreads();

    size_t ob = ((size_t)nd * 192 + h0) * 184;
    for (int i = tid; i < 16 * 91; i += 256) {
        int r = i / 91;
        int p = (i % 91) * 2;          // ow pair: p, p+1
        float a0l = 0.f, a1l = 0.f, a2l = 0.f, a3l = 0.f, a4l = 0.f;
        float a0h = 0.f, a1h = 0.f, a2h = 0.f, a3h = 0.f, a4h = 0.f;
        #pragma unroll
        for (int k = 0; k < 11; k++) {
            float g = CG[k];
            float x = sx[r * 192 + p + k];
            float y = sy[r * 192 + p + k];
            float tx = g * x, ty = g * y;
            a0l += tx; a1l += ty; a2l += tx * x; a3l += ty * y; a4l += tx * y;
            float x2 = sx[r * 192 + p + 1 + k];
            float y2 = sy[r * 192 + p + 1 + k];
            float tx2 = g * x2, ty2 = g * y2;
            a0h += tx2; a1h += ty2; a2h += tx2 * x2; a3h += ty2 * y2; a4h += tx2 * y2;
        }
        size_t o = ob + (size_t)r * 184 + p;
        *(__half2*)&d_s1[o]           = __floats2half2_rn(a0l, a0h);
        *(__half2*)&d_s1[FS1 + o]     = __floats2half2_rn(a1l, a1h);
        *(__half2*)&d_s1[2 * FS1 + o] = __floats2half2_rn(a2l, a2h);
        *(__half2*)&d_s1[3 * FS1 + o] = __floats2half2_rn(a3l, a3h);
        *(__half2*)&d_s1[4 * FS1 + o] = __floats2half2_rn(a4l, a4h);
    }

    // min/max block reduce -> atomics
    #pragma unroll
    for (int off = 16; off; off >>= 1) {
        lmin = min(lmin, __shfl_down_sync(0xFFFFFFFFu, lmin, off));
        lmax = max(lmax, __shfl_down_sync(0xFFFFFFFFu, lmax, off));
    }
    __shared__ unsigned smin[8], smax[8];
    int wid = tid >> 5, lane = tid & 31;
    if (lane == 0) { smin[wid] = lmin; smax[wid] = lmax; }
    __syncthreads();
    if (tid == 0) {
        #pragma unroll
        for (int i = 1; i < 8; i++) {
            lmin = min(lmin, smin[i]);
            lmax = max(lmax, smax[i]);
        }
        atomicMin(&d_minbits, lmin);
        atomicMax(&d_maxbits, lmax);
    }
}

// ---------------------------------------------------------------------------
// Pass 2: H conv, half2 loads, fp32 accumulation (52 accums), strips of 26.
// Thread = (nd desc, f, strip, owp). 36 half2 loads -> 26 half2 outputs.
// ---------------------------------------------------------------------------
__global__ void __launch_bounds__(256) pass2_kernel() {
    const size_t TOT = (size_t)5 * 2 * 192 * 7 * 91;     // 1,223,040
    size_t idx = (size_t)blockIdx.x * 256 + threadIdx.x;
    if (idx >= TOT) return;
    int owp = (int)(idx % 91); size_t t = idx / 91;
    int strip = (int)(t % 7); t /= 7;
    int f   = (int)(t % 5);
    int nd  = 383 - (int)(t / 5);        // descending: hit pass1's L2 tail
    int h0 = strip * 26;
    int ow = owp * 2;

    const __half* __restrict__ src = d_s1 + (size_t)f * FS1 + (size_t)nd * (192 * 184) + ow;
    __half* __restrict__ dst = d_s2 + (size_t)f * FS2 + (size_t)nd * (182 * 184) + ow;

    float accl[26], acch[26];
    #pragma unroll
    for (int o = 0; o < 26; o++) { accl[o] = 0.f; acch[o] = 0.f; }

    #pragma unroll
    for (int j = 0; j < 36; j++) {
        __half2 h = __ldg((const __half2*)&src[(size_t)(h0 + j) * 184]);
        float vl = __low2float(h), vh = __high2float(h);
        #pragma unroll
        for (int o = 0; o < 26; o++) {
            int k = j - o;
            if (k >= 0 && k < 11) {
                accl[o] += CG[k] * vl;
                acch[o] += CG[k] * vh;
            }
        }
    }
    #pragma unroll
    for (int o = 0; o < 26; o++)
        *(__half2*)&dst[(size_t)(h0 + o) * 184] = __floats2half2_rn(accl[o], acch[o]);
}

// ---------------------------------------------------------------------------
// Pass 3: D conv (5 fields) + SSIM + block sum. Thread = (n, strip, oh, ow).
// Strips of 7 (182 = 26*7): 35 fp32 accums -> ~64 regs -> high occupancy.
// 17 x 5 scalar-half loads per thread, fully coalesced within the warp.
// ---------------------------------------------------------------------------
__global__ void __launch_bounds__(256) pass3_kernel() {
    const size_t TOT = (size_t)2 * 26 * 182 * 182;   // 1,722,448
    size_t idx = (size_t)blockIdx.x * 256 + threadIdx.x;
    float lsum = 0.f;
    if (idx < TOT) {
        int ow = (int)(idx % 182); size_t t = idx / 182;
        int oh = (int)(t % 182); t /= 182;
        int strip = (int)(t % 26);
        int n = (int)(t / 26);
        int d0 = strip * 7;
        const float C1 = d_c1c2[0];
        const float C2 = d_c1c2[1];

        float a0[7], a1[7], a2[7], a3[7], a4[7];
        #pragma unroll
        for (int o = 0; o < 7; o++) {
            a0[o] = 0.f; a1[o] = 0.f; a2[o] = 0.f; a3[o] = 0.f; a4[o] = 0.f;
        }
        // s2 offset: ((n*192 + d)*182 + oh)*184 + ow ; d-stride = 182*184 = 33488
        size_t pbase = ((size_t)(n * 192 + d0) * 182 + oh) * 184 + ow;
        #pragma unroll
        for (int j = 0; j < 17; j++) {
            size_t p = pbase + (size_t)j * 33488;
            float m1  = __half2float(__ldg(&d_s2[p]));
            float m2  = __half2float(__ldg(&d_s2[p + FS2]));
            float e11 = __half2float(__ldg(&d_s2[p + 2 * FS2]));
            float e22 = __half2float(__ldg(&d_s2[p + 3 * FS2]));
            float e12 = __half2float(__ldg(&d_s2[p + 4 * FS2]));
            #pragma unroll
            for (int o = 0; o < 7; o++) {
                int k = j - o;
                if (k >= 0 && k < 11) {
                    float g = CG[k];
                    a0[o] += g * m1;
                    a1[o] += g * m2;
                    a2[o] += g * e11;
                    a3[o] += g * e22;
                    a4[o] += g * e12;
                }
            }
        }
        #pragma unroll
        for (int o = 0; o < 7; o++) {
            float mu1 = a0[o], mu2 = a1[o];
            float m11 = mu1 * mu1, m22 = mu2 * mu2, m12 = mu1 * mu2;
            float s11 = a2[o] - m11;
            float s22 = a3[o] - m22;
            float s12 = a4[o] - m12;
            float v1 = 2.f * s12 + C2;
            float v2 = s11 + s22 + C2;
            float num = (2.f * m12 + C1) * v1;
            float den = (m11 + m22 + C1) * v2;
            lsum += __fdividef(num, den);
        }
    }
    __shared__ float sred[256];
    sred[threadIdx.x] = lsum;
    __syncthreads();
    #pragma unroll
    for (int off = 128; off; off >>= 1) {
        if (threadIdx.x < off) sred[threadIdx.x] += sred[threadIdx.x + off];
        __syncthreads();
    }
    if (threadIdx.x == 0) d_bsum[blockIdx.x] = sred[0];
}

// Deterministic final reduction over 6729 block sums.
__global__ void final_kernel(float* __restrict__ out) {
    __shared__ double sd[256];
    double s = 0.0;
    for (int i = threadIdx.x; i < 6729; i += 256) s += (double)d_bsum[i];
    sd[threadIdx.x] = s;
    __syncthreads();
    #pragma unroll
    for (int off = 128; off; off >>= 1) {
        if (threadIdx.x < off) sd[threadIdx.x] += sd[threadIdx.x + off];
        __syncthreads();
    }
    if (threadIdx.x == 0)
        out[0] = (float)(sd[0] / 12057136.0);   // 2 * 182^3
}

// ---------------------------------------------------------------------------

extern "C" void kernel_launch(void* const* d_in, const int* in_sizes, int n_in,
                              void* d_out, int out_size) {
    const float* img1 = (const float*)d_in[0];
    const float* img2 = (const float*)d_in[1];
    float* out = (float*)d_out;

    init_kernel<<<1, 1>>>();
    pass1_kernel<<<4608, 256>>>(img1, img2);   // 2*192*192 rows / 16
    const_kernel<<<1, 1>>>();
    pass2_kernel<<<4778, 256>>>();             // 5*2*192*7*91 threads (half2)
    pass3_kernel<<<6729, 256>>>();             // 2*26*182*182 threads (strip 7)
    final_kernel<<<1, 256>>>(out);
}

// round 10
// speedup vs baseline: 1.0435x; 1.0435x over previous
#include <cuda_runtime.h>
#include <cuda_fp16.h>

// ---------------------------------------------------------------------------
// SSIM 3D, 11-tap separable Gaussian, VALID. Round 10:
// R7 shapes/numerics + packed fp32 math (fma.rn.f32x2) -> half the FMA
// instruction stream at identical fp32 rounding.
// ---------------------------------------------------------------------------

typedef unsigned long long ull;

__device__ constexpr float CG[11] = {
    0.0010283817f, 0.0075987700f, 0.0360007700f, 0.1093607000f,
    0.2130055500f, 0.2660117200f,
    0.2130055500f, 0.1093607000f, 0.0360007700f, 0.0075987700f,
    0.0010283817f
};

__device__ __forceinline__ ull f2pack(float lo, float hi) {
    ull r; asm("mov.b64 %0, {%1, %2};" : "=l"(r) : "f"(lo), "f"(hi)); return r;
}
__device__ __forceinline__ float2 f2unpack(ull v) {
    float2 r; asm("mov.b64 {%0, %1}, %2;" : "=f"(r.x), "=f"(r.y) : "l"(v)); return r;
}
__device__ __forceinline__ ull f2fma(ull a, ull b, ull c) {
    ull d; asm("fma.rn.f32x2 %0, %1, %2, %3;" : "=l"(d) : "l"(a), "l"(b), "l"(c)); return d;
}
__device__ __forceinline__ ull f2mul(ull a, ull b) {
    ull d; asm("mul.rn.f32x2 %0, %1, %2;" : "=l"(d) : "l"(a), "l"(b)); return d;
}

// s1: [f][n][d][h(192)][w(184 pad, 182 valid)]   half
// s2: [f][n][d][oh(182)][w(184 pad, 182 valid)]  half
static const size_t FS1 = (size_t)2 * 192 * 192 * 184;   // 13,565,952 halves
static const size_t FS2 = (size_t)2 * 192 * 182 * 184;   // 12,859,392 halves
__device__ __half d_s1[5 * FS1];
__device__ __half d_s2[5 * FS2];

__device__ unsigned d_minbits;
__device__ unsigned d_maxbits;
__device__ float    d_c1c2[2];
__device__ float    d_bsum[3623];

// ---------------------------------------------------------------------------

__global__ void init_kernel() {
    d_minbits = 0xFFFFFFFFu;
    d_maxbits = 0u;
}

__device__ __forceinline__ float mono2f(unsigned u) {
    return (u & 0x80000000u) ? __uint_as_float(u ^ 0x80000000u)
                             : __uint_as_float(~u);
}
__device__ __forceinline__ void mono_acc(float f, unsigned& mn, unsigned& mx) {
    unsigned u = __float_as_uint(f);
    u = (u & 0x80000000u) ? ~u : (u | 0x80000000u);
    mn = min(mn, u);
    mx = max(mx, u);
}

__global__ void const_kernel() {
    float mx = mono2f(d_maxbits);
    float mn = mono2f(d_minbits);
    float max_val = (mx > 128.0f) ? 255.0f : 1.0f;
    float min_val = (mn < -0.5f) ? -1.0f : 0.0f;
    float L = max_val - min_val;
    float c1 = 0.01f * L, c2 = 0.03f * L;
    d_c1c2[0] = c1 * c1;
    d_c1c2[1] = c2 * c2;
}

// ---------------------------------------------------------------------------
// Pass 1: W conv + 5 products + img1 min/max. Block = (n,d, 8 h-rows).
// 192 threads; float4 smem fill; f32x2 packed taps; half2 stores.
// ---------------------------------------------------------------------------
__global__ void __launch_bounds__(192) pass1_kernel(
    const float* __restrict__ img1, const float* __restrict__ img2) {
    __shared__ float sx[8 * 192];
    __shared__ float sy[8 * 192];

    int hg = blockIdx.x % 24;
    int nd = blockIdx.x / 24;          // n*192 + d
    int h0 = hg * 8;
    size_t base = ((size_t)nd * 192 + h0) * 192;
    int tid = threadIdx.x;

    unsigned lmin = 0xFFFFFFFFu, lmax = 0u;
    const float4* p1 = (const float4*)(img1 + base);
    const float4* p2 = (const float4*)(img2 + base);
    #pragma unroll
    for (int j = 0; j < 2; j++) {
        int idx = tid + j * 192;       // 0..383 float4
        float4 a = __ldg(&p1[idx]);
        float4 b = __ldg(&p2[idx]);
        ((float4*)sx)[idx] = a;
        ((float4*)sy)[idx] = b;
        mono_acc(a.x, lmin, lmax); mono_acc(a.y, lmin, lmax);
        mono_acc(a.z, lmin, lmax); mono_acc(a.w, lmin, lmax);
    }
    __syncthreads();

    size_t ob = ((size_t)nd * 192 + h0) * 184;
    for (int i = tid; i < 8 * 91; i += 192) {
        int r = i / 91;
        int p = (i % 91) * 2;          // ow pair: p, p+1 (p even)
        // load the 12-float windows (float2: p even => 8B aligned)
        float xw[12], yw[12];
        #pragma unroll
        for (int q = 0; q < 6; q++) {
            float2 tx = *(const float2*)&sx[r * 192 + p + 2 * q];
            float2 ty = *(const float2*)&sy[r * 192 + p + 2 * q];
            xw[2 * q] = tx.x; xw[2 * q + 1] = tx.y;
            yw[2 * q] = ty.x; yw[2 * q + 1] = ty.y;
        }
        ull A0 = 0, A1 = 0, A2 = 0, A3 = 0, A4 = 0;
        #pragma unroll
        for (int k = 0; k < 11; k++) {
            ull G = f2pack(CG[k], CG[k]);
            ull X = f2pack(xw[k], xw[k + 1]);
            ull Y = f2pack(yw[k], yw[k + 1]);
            ull TX = f2mul(G, X);
            ull TY = f2mul(G, Y);
            A0 = f2fma(G, X, A0);
            A1 = f2fma(G, Y, A1);
            A2 = f2fma(TX, X, A2);
            A3 = f2fma(TY, Y, A3);
            A4 = f2fma(TX, Y, A4);
        }
        size_t o = ob + (size_t)r * 184 + p;
        float2 v;
        v = f2unpack(A0); *(__half2*)&d_s1[o]           = __floats2half2_rn(v.x, v.y);
        v = f2unpack(A1); *(__half2*)&d_s1[FS1 + o]     = __floats2half2_rn(v.x, v.y);
        v = f2unpack(A2); *(__half2*)&d_s1[2 * FS1 + o] = __floats2half2_rn(v.x, v.y);
        v = f2unpack(A3); *(__half2*)&d_s1[3 * FS1 + o] = __floats2half2_rn(v.x, v.y);
        v = f2unpack(A4); *(__half2*)&d_s1[4 * FS1 + o] = __floats2half2_rn(v.x, v.y);
    }

    // min/max block reduce -> atomics
    #pragma unroll
    for (int off = 16; off; off >>= 1) {
        lmin = min(lmin, __shfl_down_sync(0xFFFFFFFFu, lmin, off));
        lmax = max(lmax, __shfl_down_sync(0xFFFFFFFFu, lmax, off));
    }
    __shared__ unsigned smin[6], smax[6];
    int wid = tid >> 5, lane = tid & 31;
    if (lane == 0) { smin[wid] = lmin; smax[wid] = lmax; }
    __syncthreads();
    if (tid == 0) {
        #pragma unroll
        for (int i = 1; i < 6; i++) {
            lmin = min(lmin, smin[i]);
            lmax = max(lmax, smax[i]);
        }
        atomicMin(&d_minbits, lmin);
        atomicMax(&d_maxbits, lmax);
    }
}

// ---------------------------------------------------------------------------
// Pass 2: H conv, half2 loads, f32x2 accumulation (26 packed accums),
// strips of 26. Thread = (nd desc, f, strip, owp).
// ---------------------------------------------------------------------------
__global__ void __launch_bounds__(256) pass2_kernel() {
    const size_t TOT = (size_t)5 * 2 * 192 * 7 * 91;     // 1,223,040
    size_t idx = (size_t)blockIdx.x * 256 + threadIdx.x;
    if (idx >= TOT) return;
    int owp = (int)(idx % 91); size_t t = idx / 91;
    int strip = (int)(t % 7); t /= 7;
    int f   = (int)(t % 5);
    int nd  = 383 - (int)(t / 5);        // descending: hit pass1's L2 tail
    int h0 = strip * 26;
    int ow = owp * 2;

    const __half* __restrict__ src = d_s1 + (size_t)f * FS1 + (size_t)nd * (192 * 184) + ow;
    __half* __restrict__ dst = d_s2 + (size_t)f * FS2 + (size_t)nd * (182 * 184) + ow;

    ull acc[26];
    #pragma unroll
    for (int o = 0; o < 26; o++) acc[o] = 0;

    #pragma unroll
    for (int j = 0; j < 36; j++) {
        __half2 h = __ldg((const __half2*)&src[(size_t)(h0 + j) * 184]);
        float2 vf = __half22float2(h);
        ull v2 = f2pack(vf.x, vf.y);
        #pragma unroll
        for (int o = 0; o < 26; o++) {
            int k = j - o;
            if (k >= 0 && k < 11)
                acc[o] = f2fma(f2pack(CG[k], CG[k]), v2, acc[o]);
        }
    }
    #pragma unroll
    for (int o = 0; o < 26; o++) {
        float2 v = f2unpack(acc[o]);
        *(__half2*)&dst[(size_t)(h0 + o) * 184] = __floats2half2_rn(v.x, v.y);
    }
}

// ---------------------------------------------------------------------------
// Pass 3: D conv (5 fields) + SSIM + block sum. Thread = (n, strip, oh, ow).
// Strips of 13; outputs packed in pairs (2p, 2p+1) -> f32x2 accumulators with
// compile-time coefficient pairs {CG[j-2p], CG[j-2p-1]}.
// ---------------------------------------------------------------------------
__global__ void __launch_bounds__(256) pass3_kernel() {
    const size_t TOT = (size_t)2 * 14 * 182 * 182;   // 927,472
    size_t idx = (size_t)blockIdx.x * 256 + threadIdx.x;
    float lsum = 0.f;
    if (idx < TOT) {
        int ow = (int)(idx % 182); size_t t = idx / 182;
        int oh = (int)(t % 182); t /= 182;
        int strip = (int)(t % 14);
        int n = (int)(t / 14);
        int d0 = strip * 13;
        const float C1 = d_c1c2[0];
        const float C2 = d_c1c2[1];

        ull a0[7], a1[7], a2[7], a3[7], a4[7];
        #pragma unroll
        for (int p = 0; p < 7; p++) {
            a0[p] = 0; a1[p] = 0; a2[p] = 0; a3[p] = 0; a4[p] = 0;
        }
        // s2 offset: ((n*192 + d)*182 + oh)*184 + ow ; d-stride = 182*184 = 33488
        size_t pbase = ((size_t)(n * 192 + d0) * 182 + oh) * 184 + ow;
        #pragma unroll
        for (int j = 0; j < 23; j++) {
            size_t pp = pbase + (size_t)j * 33488;
            float m1  = __half2float(__ldg(&d_s2[pp]));
            float m2  = __half2float(__ldg(&d_s2[pp + FS2]));
            float e11 = __half2float(__ldg(&d_s2[pp + 2 * FS2]));
            float e22 = __half2float(__ldg(&d_s2[pp + 3 * FS2]));
            float e12 = __half2float(__ldg(&d_s2[pp + 4 * FS2]));
            ull M1 = f2pack(m1, m1);
            ull M2 = f2pack(m2, m2);
            ull E11 = f2pack(e11, e11);
            ull E22 = f2pack(e22, e22);
            ull E12 = f2pack(e12, e12);
            #pragma unroll
            for (int p = 0; p < 7; p++) {
                const int klo = j - 2 * p;
                const int khi = klo - 1;
                const bool vlo = (klo >= 0 && klo < 11);
                const bool vhi = (khi >= 0 && khi < 11);
                if (vlo || vhi) {
                    float glo = vlo ? CG[klo] : 0.f;
                    float ghi = vhi ? CG[khi] : 0.f;
                    ull G = f2pack(glo, ghi);
                    a0[p] = f2fma(G, M1,  a0[p]);
                    a1[p] = f2fma(G, M2,  a1[p]);
                    a2[p] = f2fma(G, E11, a2[p]);
                    a3[p] = f2fma(G, E22, a3[p]);
                    a4[p] = f2fma(G, E12, a4[p]);
                }
            }
        }
        #pragma unroll
        for (int p = 0; p < 7; p++) {
            float2 MU1 = f2unpack(a0[p]);
            float2 MU2 = f2unpack(a1[p]);
            float2 S11 = f2unpack(a2[p]);
            float2 S22 = f2unpack(a3[p]);
            float2 S12 = f2unpack(a4[p]);
            const int nlane = (p == 6) ? 1 : 2;   // 13 outputs: pair 6 lo only
            #pragma unroll
            for (int l = 0; l < 2; l++) {
                if (l >= nlane) break;
                float mu1 = l ? MU1.y : MU1.x;
                float mu2 = l ? MU2.y : MU2.x;
                float e11 = l ? S11.y : S11.x;
                float e22 = l ? S22.y : S22.x;
                float e12 = l ? S12.y : S12.x;
                float m11 = mu1 * mu1, m22 = mu2 * mu2, m12 = mu1 * mu2;
                float s11 = e11 - m11;
                float s22 = e22 - m22;
                float s12 = e12 - m12;
                float v1 = 2.f * s12 + C2;
                float v2 = s11 + s22 + C2;
                float num = (2.f * m12 + C1) * v1;
                float den = (m11 + m22 + C1) * v2;
                lsum += __fdividef(num, den);
            }
        }
    }
    __shared__ float sred[256];
    sred[threadIdx.x] = lsum;
    __syncthreads();
    #pragma unroll
    for (int off = 128; off; off >>= 1) {
        if (threadIdx.x < off) sred[threadIdx.x] += sred[threadIdx.x + off];
        __syncthreads();
    }
    if (threadIdx.x == 0) d_bsum[blockIdx.x] = sred[0];
}

// Deterministic final reduction over 3623 block sums.
__global__ void final_kernel(float* __restrict__ out) {
    __shared__ double sd[256];
    double s = 0.0;
    for (int i = threadIdx.x; i < 3623; i += 256) s += (double)d_bsum[i];
    sd[threadIdx.x] = s;
    __syncthreads();
    #pragma unroll
    for (int off = 128; off; off >>= 1) {
        if (threadIdx.x < off) sd[threadIdx.x] += sd[threadIdx.x + off];
        __syncthreads();
    }
    if (threadIdx.x == 0)
        out[0] = (float)(sd[0] / 12057136.0);   // 2 * 182^3
}

// ---------------------------------------------------------------------------

extern "C" void kernel_launch(void* const* d_in, const int* in_sizes, int n_in,
                              void* d_out, int out_size) {
    const float* img1 = (const float*)d_in[0];
    const float* img2 = (const float*)d_in[1];
    float* out = (float*)d_out;

    init_kernel<<<1, 1>>>();
    pass1_kernel<<<9216, 192>>>(img1, img2);   // 2*192*192 rows / 8
    const_kernel<<<1, 1>>>();
    pass2_kernel<<<4778, 256>>>();             // 5*2*192*7*91 threads
    pass3_kernel<<<3623, 256>>>();             // 2*14*182*182 threads
    final_kernel<<<1, 256>>>(out);
}

// round 11
// speedup vs baseline: 1.1117x; 1.0654x over previous
#include <cuda_runtime.h>
#include <cuda_fp16.h>

// ---------------------------------------------------------------------------
// SSIM 3D, 11-tap separable Gaussian, VALID. Round 11:
// R7 structure/numerics (fp32 accumulate, fp16 storage) +
//   - scratch rows padded to 192 halves (384B = 3 full 128B lines): every
//     warp request sector/line aligned
//   - const_kernel folded into pass3 (one less launch)
// ---------------------------------------------------------------------------

__device__ constexpr float CG[11] = {
    0.0010283817f, 0.0075987700f, 0.0360007700f, 0.1093607000f,
    0.2130055500f, 0.2660117200f,
    0.2130055500f, 0.1093607000f, 0.0360007700f, 0.0075987700f,
    0.0010283817f
};

// s1: [f][n][d][h(192)][w(192 pad, 182 valid)]   half
// s2: [f][n][d][oh(182)][w(192 pad, 182 valid)]  half
static const size_t FS1 = (size_t)2 * 192 * 192 * 192;   // 14,155,776 halves
static const size_t FS2 = (size_t)2 * 192 * 182 * 192;   // 13,418,496 halves
__device__ __half d_s1[5 * FS1];
__device__ __half d_s2[5 * FS2];

__device__ unsigned d_minbits;
__device__ unsigned d_maxbits;
__device__ float    d_bsum[3623];

// ---------------------------------------------------------------------------

__global__ void init_kernel() {
    d_minbits = 0xFFFFFFFFu;
    d_maxbits = 0u;
}

__device__ __forceinline__ float mono2f(unsigned u) {
    return (u & 0x80000000u) ? __uint_as_float(u ^ 0x80000000u)
                             : __uint_as_float(~u);
}
__device__ __forceinline__ void mono_acc(float f, unsigned& mn, unsigned& mx) {
    unsigned u = __float_as_uint(f);
    u = (u & 0x80000000u) ? ~u : (u | 0x80000000u);
    mn = min(mn, u);
    mx = max(mx, u);
}

// ---------------------------------------------------------------------------
// Pass 1: W conv + 5 products + img1 min/max. Block = (n,d, 8 h-rows).
// 192 threads; float4 smem fill; half2 stores to 192-padded rows.
// ---------------------------------------------------------------------------
__global__ void __launch_bounds__(192) pass1_kernel(
    const float* __restrict__ img1, const float* __restrict__ img2) {
    __shared__ float sx[8 * 192];
    __shared__ float sy[8 * 192];

    int hg = blockIdx.x % 24;
    int nd = blockIdx.x / 24;          // n*192 + d
    int h0 = hg * 8;
    size_t base = ((size_t)nd * 192 + h0) * 192;
    int tid = threadIdx.x;

    unsigned lmin = 0xFFFFFFFFu, lmax = 0u;
    const float4* p1 = (const float4*)(img1 + base);
    const float4* p2 = (const float4*)(img2 + base);
    #pragma unroll
    for (int j = 0; j < 2; j++) {
        int idx = tid + j * 192;       // 0..383 float4
        float4 a = __ldg(&p1[idx]);
        float4 b = __ldg(&p2[idx]);
        ((float4*)sx)[idx] = a;
        ((float4*)sy)[idx] = b;
        mono_acc(a.x, lmin, lmax); mono_acc(a.y, lmin, lmax);
        mono_acc(a.z, lmin, lmax); mono_acc(a.w, lmin, lmax);
    }
    __syncthreads();

    size_t ob = base;                  // 192-padded: same linear layout as input
    for (int i = tid; i < 8 * 91; i += 192) {
        int r = i / 91;
        int p = (i % 91) * 2;          // ow pair: p, p+1
        float a0l = 0.f, a1l = 0.f, a2l = 0.f, a3l = 0.f, a4l = 0.f;
        float a0h = 0.f, a1h = 0.f, a2h = 0.f, a3h = 0.f, a4h = 0.f;
        #pragma unroll
        for (int k = 0; k < 11; k++) {
            float g = CG[k];
            float x = sx[r * 192 + p + k];
            float y = sy[r * 192 + p + k];
            float tx = g * x, ty = g * y;
            a0l += tx; a1l += ty; a2l += tx * x; a3l += ty * y; a4l += tx * y;
            float x2 = sx[r * 192 + p + 1 + k];
            float y2 = sy[r * 192 + p + 1 + k];
            float tx2 = g * x2, ty2 = g * y2;
            a0h += tx2; a1h += ty2; a2h += tx2 * x2; a3h += ty2 * y2; a4h += tx2 * y2;
        }
        size_t o = ob + (size_t)r * 192 + p;
        *(__half2*)&d_s1[o]           = __floats2half2_rn(a0l, a0h);
        *(__half2*)&d_s1[FS1 + o]     = __floats2half2_rn(a1l, a1h);
        *(__half2*)&d_s1[2 * FS1 + o] = __floats2half2_rn(a2l, a2h);
        *(__half2*)&d_s1[3 * FS1 + o] = __floats2half2_rn(a3l, a3h);
        *(__half2*)&d_s1[4 * FS1 + o] = __floats2half2_rn(a4l, a4h);
    }

    // min/max block reduce -> atomics
    #pragma unroll
    for (int off = 16; off; off >>= 1) {
        lmin = min(lmin, __shfl_down_sync(0xFFFFFFFFu, lmin, off));
        lmax = max(lmax, __shfl_down_sync(0xFFFFFFFFu, lmax, off));
    }
    __shared__ unsigned smin[6], smax[6];
    int wid = tid >> 5, lane = tid & 31;
    if (lane == 0) { smin[wid] = lmin; smax[wid] = lmax; }
    __syncthreads();
    if (tid == 0) {
        #pragma unroll
        for (int i = 1; i < 6; i++) {
            lmin = min(lmin, smin[i]);
            lmax = max(lmax, smax[i]);
        }
        atomicMin(&d_minbits, lmin);
        atomicMax(&d_maxbits, lmax);
    }
}

// ---------------------------------------------------------------------------
// Pass 2: H conv, half2 loads, fp32 accumulation (52 accums), strips of 26.
// Thread = (nd desc, f, strip, owp). 36 half2 loads -> 26 half2 outputs.
// ---------------------------------------------------------------------------
__global__ void __launch_bounds__(256) pass2_kernel() {
    const size_t TOT = (size_t)5 * 2 * 192 * 7 * 91;     // 1,223,040
    size_t idx = (size_t)blockIdx.x * 256 + threadIdx.x;
    if (idx >= TOT) return;
    int owp = (int)(idx % 91); size_t t = idx / 91;
    int strip = (int)(t % 7); t /= 7;
    int f   = (int)(t % 5);
    int nd  = 383 - (int)(t / 5);        // descending: hit pass1's L2 tail
    int h0 = strip * 26;
    int ow = owp * 2;

    const __half* __restrict__ src = d_s1 + (size_t)f * FS1 + (size_t)nd * (192 * 192) + ow;
    __half* __restrict__ dst = d_s2 + (size_t)f * FS2 + (size_t)nd * (182 * 192) + ow;

    float accl[26], acch[26];
    #pragma unroll
    for (int o = 0; o < 26; o++) { accl[o] = 0.f; acch[o] = 0.f; }

    #pragma unroll
    for (int j = 0; j < 36; j++) {
        __half2 h = __ldg((const __half2*)&src[(size_t)(h0 + j) * 192]);
        float vl = __low2float(h), vh = __high2float(h);
        #pragma unroll
        for (int o = 0; o < 26; o++) {
            int k = j - o;
            if (k >= 0 && k < 11) {
                accl[o] += CG[k] * vl;
                acch[o] += CG[k] * vh;
            }
        }
    }
    #pragma unroll
    for (int o = 0; o < 26; o++)
        *(__half2*)&dst[(size_t)(h0 + o) * 192] = __floats2half2_rn(accl[o], acch[o]);
}

// ---------------------------------------------------------------------------
// Pass 3: D conv (5 fields) + SSIM + block sum. Thread = (n, strip, oh, ow).
// Strips of 13 (182 = 14*13), 23 loads x 5 fields, 65 fp32 accumulators.
// C1/C2 derived inline from min/max bits (const_kernel folded in).
// ---------------------------------------------------------------------------
__global__ void __launch_bounds__(256) pass3_kernel() {
    const size_t TOT = (size_t)2 * 14 * 182 * 182;   // 927,472
    size_t idx = (size_t)blockIdx.x * 256 + threadIdx.x;
    float lsum = 0.f;
    if (idx < TOT) {
        int ow = (int)(idx % 182); size_t t = idx / 182;
        int oh = (int)(t % 182); t /= 182;
        int strip = (int)(t % 14);
        int n = (int)(t / 14);
        int d0 = strip * 13;

        float mx = mono2f(d_maxbits);
        float mn = mono2f(d_minbits);
        float max_val = (mx > 128.0f) ? 255.0f : 1.0f;
        float min_val = (mn < -0.5f) ? -1.0f : 0.0f;
        float L = max_val - min_val;
        float c1 = 0.01f * L, c2 = 0.03f * L;
        const float C1 = c1 * c1;
        const float C2 = c2 * c2;

        float a0[13], a1[13], a2[13], a3[13], a4[13];
        #pragma unroll
        for (int o = 0; o < 13; o++) {
            a0[o] = 0.f; a1[o] = 0.f; a2[o] = 0.f; a3[o] = 0.f; a4[o] = 0.f;
        }
        // s2 offset: ((n*192 + d)*182 + oh)*192 + ow ; d-stride = 182*192 = 34944
        size_t pbase = ((size_t)(n * 192 + d0) * 182 + oh) * 192 + ow;
        #pragma unroll
        for (int j = 0; j < 23; j++) {
            size_t p = pbase + (size_t)j * 34944;
            float m1  = __half2float(__ldg(&d_s2[p]));
            float m2  = __half2float(__ldg(&d_s2[p + FS2]));
            float e11 = __half2float(__ldg(&d_s2[p + 2 * FS2]));
            float e22 = __half2float(__ldg(&d_s2[p + 3 * FS2]));
            float e12 = __half2float(__ldg(&d_s2[p + 4 * FS2]));
            #pragma unroll
            for (int o = 0; o < 13; o++) {
                int k = j - o;
                if (k >= 0 && k < 11) {
                    float g = CG[k];
                    a0[o] += g * m1;
                    a1[o] += g * m2;
                    a2[o] += g * e11;
                    a3[o] += g * e22;
                    a4[o] += g * e12;
                }
            }
        }
        #pragma unroll
        for (int o = 0; o < 13; o++) {
            float mu1 = a0[o], mu2 = a1[o];
            float m11 = mu1 * mu1, m22 = mu2 * mu2, m12 = mu1 * mu2;
            float s11 = a2[o] - m11;
            float s22 = a3[o] - m22;
            float s12 = a4[o] - m12;
            float v1 = 2.f * s12 + C2;
            float v2 = s11 + s22 + C2;
            float num = (2.f * m12 + C1) * v1;
            float den = (m11 + m22 + C1) * v2;
            lsum += __fdividef(num, den);
        }
    }
    __shared__ float sred[256];
    sred[threadIdx.x] = lsum;
    __syncthreads();
    #pragma unroll
    for (int off = 128; off; off >>= 1) {
        if (threadIdx.x < off) sred[threadIdx.x] += sred[threadIdx.x + off];
        __syncthreads();
    }
    if (threadIdx.x == 0) d_bsum[blockIdx.x] = sred[0];
}

// Deterministic final reduction over 3623 block sums.
__global__ void final_kernel(float* __restrict__ out) {
    __shared__ double sd[256];
    double s = 0.0;
    for (int i = threadIdx.x; i < 3623; i += 256) s += (double)d_bsum[i];
    sd[threadIdx.x] = s;
    __syncthreads();
    #pragma unroll
    for (int off = 128; off; off >>= 1) {
        if (threadIdx.x < off) sd[threadIdx.x] += sd[threadIdx.x + off];
        __syncthreads();
    }
    if (threadIdx.x == 0)
        out[0] = (float)(sd[0] / 12057136.0);   // 2 * 182^3
}

// ---------------------------------------------------------------------------

extern "C" void kernel_launch(void* const* d_in, const int* in_sizes, int n_in,
                              void* d_out, int out_size) {
    const float* img1 = (const float*)d_in[0];
    const float* img2 = (const float*)d_in[1];
    float* out = (float*)d_out;

    init_kernel<<<1, 1>>>();
    pass1_kernel<<<9216, 192>>>(img1, img2);   // 2*192*192 rows / 8
    pass2_kernel<<<4778, 256>>>();             // 5*2*192*7*91 threads
    pass3_kernel<<<3623, 256>>>();             // 2*14*182*182 threads
    final_kernel<<<1, 256>>>(out);
}